// round 1
// baseline (speedup 1.0000x reference)
#include <cuda_runtime.h>
#include <math.h>

// Problem constants
#define Bz   8
#define Tz   4096
#define Dz   512
#define HIDz 1024
#define Kz   5
#define NTOK (Bz * Tz)          // 32768
#define CH   16                 // scan chunks
#define LCH  (Tz / CH)          // 256

// ---------------- scratch (static device globals; no runtime alloc) -------
__device__ float g_xn[(size_t)NTOK * Dz];    // LN1 output, later LN2 output
__device__ float g_ss[(size_t)NTOK * Dz];    // retention states
__device__ float g_x1[(size_t)NTOK * Dz];    // x + y (mid residual)
__device__ float g_h [(size_t)NTOK * HIDz];  // MLP hidden
__device__ float g_lend [Bz * CH * Dz];      // chunk-local scan ends
__device__ float g_carry[Bz * CH * Dz];      // chunk carry-ins

// ---------------- layernorm: one block (128 thr) per token ----------------
__global__ void ln_kernel(const float* __restrict__ xin,
                          const float* __restrict__ gam,
                          const float* __restrict__ bet,
                          float* __restrict__ outp) {
    int tok = blockIdx.x;
    const float4* xr = (const float4*)(xin + (size_t)tok * Dz);
    float4 v = xr[threadIdx.x];
    float s  = v.x + v.y + v.z + v.w;
    float s2 = v.x*v.x + v.y*v.y + v.z*v.z + v.w*v.w;

    __shared__ float sh[8];
    #pragma unroll
    for (int o = 16; o > 0; o >>= 1) {
        s  += __shfl_down_sync(0xffffffffu, s,  o);
        s2 += __shfl_down_sync(0xffffffffu, s2, o);
    }
    int w = threadIdx.x >> 5;
    if ((threadIdx.x & 31) == 0) { sh[w] = s; sh[4 + w] = s2; }
    __syncthreads();
    __shared__ float mu_s, inv_s;
    if (threadIdx.x == 0) {
        float ts  = sh[0] + sh[1] + sh[2] + sh[3];
        float ts2 = sh[4] + sh[5] + sh[6] + sh[7];
        float mu  = ts * (1.0f / Dz);
        float var = ts2 * (1.0f / Dz) - mu * mu;
        mu_s  = mu;
        inv_s = rsqrtf(var + 1e-5f);
    }
    __syncthreads();
    float mu = mu_s, inv = inv_s;
    float4 gg = ((const float4*)gam)[threadIdx.x];
    float4 bb = ((const float4*)bet)[threadIdx.x];
    float4 o;
    o.x = (v.x - mu) * inv * gg.x + bb.x;
    o.y = (v.y - mu) * inv * gg.y + bb.y;
    o.z = (v.z - mu) * inv * gg.z + bb.z;
    o.w = (v.w - mu) * inv * gg.w + bb.w;
    ((float4*)(outp + (size_t)tok * Dz))[threadIdx.x] = o;
}

// ---------------- chunked linear scan --------------------------------------
// thread idx = b*CH*Dz + c*Dz + d  (d fastest -> coalesced over t rows)
__global__ void scan_partial(const float* __restrict__ xn,
                             const float* __restrict__ decay,
                             float* __restrict__ lend) {
    int idx = blockIdx.x * blockDim.x + threadIdx.x;
    int d = idx & (Dz - 1);
    int c = (idx >> 9) & (CH - 1);
    int b = idx >> 13;
    float a  = 1.0f / (1.0f + expf(-decay[d]));
    float na = 1.0f - a;
    const float* p = xn + ((size_t)(b * Tz + c * LCH)) * Dz + d;
    float s = 0.0f;
    #pragma unroll 8
    for (int t = 0; t < LCH; t++) s = a * s + na * p[(size_t)t * Dz];
    lend[idx] = s;
}

__global__ void scan_carry(const float* __restrict__ lend,
                           const float* __restrict__ decay,
                           float* __restrict__ carry) {
    int idx = blockIdx.x * blockDim.x + threadIdx.x;   // B*Dz threads
    int d = idx & (Dz - 1);
    int b = idx >> 9;
    float a  = 1.0f / (1.0f + expf(-decay[d]));
    float aL = powf(a, (float)LCH);
    float s = 0.0f;
    #pragma unroll
    for (int c = 0; c < CH; c++) {
        int e = (b * CH + c) * Dz + d;
        carry[e] = s;
        s = aL * s + lend[e];
    }
}

__global__ void scan_final(const float* __restrict__ xn,
                           const float* __restrict__ decay,
                           const float* __restrict__ carry,
                           float* __restrict__ ss) {
    int idx = blockIdx.x * blockDim.x + threadIdx.x;
    int d = idx & (Dz - 1);
    int c = (idx >> 9) & (CH - 1);
    int b = idx >> 13;
    float a  = 1.0f / (1.0f + expf(-decay[d]));
    float na = 1.0f - a;
    size_t base = ((size_t)(b * Tz + c * LCH)) * Dz + d;
    const float* p = xn + base;
    float* q = ss + base;
    float s = carry[idx];
    #pragma unroll 8
    for (int t = 0; t < LCH; t++) {
        s = a * s + na * p[(size_t)t * Dz];
        q[(size_t)t * Dz] = s;
    }
}

// ---------------- depthwise conv (K=5, same) added into x1 -----------------
__global__ void conv_add(const float* __restrict__ xn,
                         const float* __restrict__ cw,
                         const float* __restrict__ cb,
                         float* __restrict__ x1) {
    int idx = blockIdx.x * blockDim.x + threadIdx.x;   // NTOK*Dz
    int d  = idx & (Dz - 1);
    int g  = idx >> 9;
    int tl = g & (Tz - 1);
    float acc = cb[d];
    #pragma unroll
    for (int k = 0; k < Kz; k++) {
        int tt = tl + k - 2;
        if (tt >= 0 && tt < Tz)
            acc += __ldg(&cw[d * Kz + k]) * xn[(size_t)idx + (size_t)(k - 2) * Dz];
    }
    x1[idx] += acc;
}

// ---------------- NT SGEMM: C[M,N] = A[M,K] * W[N,K]^T + epilogue ----------
// EPI 0: out = res + acc + bias      EPI 1: out = gelu(acc + bias)
#define BM 128
#define BN 128
#define BKt 16
#define TM 8
#define TN 8

template<int EPI>
__global__ void __launch_bounds__(256)
gemm_nt(const float* __restrict__ A, const float* __restrict__ W,
        const float* __restrict__ bias, int M, int N, int Kd,
        const float* __restrict__ res, float* __restrict__ out) {
    __shared__ float As[BKt][BM + 4];
    __shared__ float Bs[BKt][BN + 4];

    int tid = threadIdx.x;
    int bm = blockIdx.y, bn = blockIdx.x;
    int tx = tid & 15, ty = tid >> 4;

    float acc[TM][TN];
    #pragma unroll
    for (int i = 0; i < TM; i++)
        #pragma unroll
        for (int j = 0; j < TN; j++) acc[i][j] = 0.0f;

    const float* Ab = A + (size_t)bm * BM * Kd;
    const float* Wb = W + (size_t)bn * BN * Kd;

    for (int kt = 0; kt < Kd; kt += BKt) {
        #pragma unroll
        for (int i = tid; i < BM * BKt / 4; i += 256) {
            int row = i >> 2, c4 = i & 3;
            float4 v = *(const float4*)(Ab + (size_t)row * Kd + kt + c4 * 4);
            As[c4 * 4 + 0][row] = v.x;
            As[c4 * 4 + 1][row] = v.y;
            As[c4 * 4 + 2][row] = v.z;
            As[c4 * 4 + 3][row] = v.w;
        }
        #pragma unroll
        for (int i = tid; i < BN * BKt / 4; i += 256) {
            int row = i >> 2, c4 = i & 3;
            float4 v = *(const float4*)(Wb + (size_t)row * Kd + kt + c4 * 4);
            Bs[c4 * 4 + 0][row] = v.x;
            Bs[c4 * 4 + 1][row] = v.y;
            Bs[c4 * 4 + 2][row] = v.z;
            Bs[c4 * 4 + 3][row] = v.w;
        }
        __syncthreads();

        #pragma unroll
        for (int k = 0; k < BKt; k++) {
            float ra[TM], rb[TN];
            *(float4*)(ra)     = *(const float4*)&As[k][ty * TM];
            *(float4*)(ra + 4) = *(const float4*)&As[k][ty * TM + 4];
            *(float4*)(rb)     = *(const float4*)&Bs[k][tx * TN];
            *(float4*)(rb + 4) = *(const float4*)&Bs[k][tx * TN + 4];
            #pragma unroll
            for (int i = 0; i < TM; i++)
                #pragma unroll
                for (int j = 0; j < TN; j++)
                    acc[i][j] = fmaf(ra[i], rb[j], acc[i][j]);
        }
        __syncthreads();
    }

    int gm0 = bm * BM + ty * TM;
    int gn0 = bn * BN + tx * TN;
    float bv[TN];
    #pragma unroll
    for (int j = 0; j < TN; j++) bv[j] = bias[gn0 + j];

    #pragma unroll
    for (int i = 0; i < TM; i++) {
        size_t ro = (size_t)(gm0 + i) * N + gn0;
        float vals[TN];
        #pragma unroll
        for (int j = 0; j < TN; j++) vals[j] = acc[i][j] + bv[j];
        if (EPI == 0) {
            float4 r0 = *(const float4*)(res + ro);
            float4 r1 = *(const float4*)(res + ro + 4);
            vals[0] += r0.x; vals[1] += r0.y; vals[2] += r0.z; vals[3] += r0.w;
            vals[4] += r1.x; vals[5] += r1.y; vals[6] += r1.z; vals[7] += r1.w;
        } else {
            #pragma unroll
            for (int j = 0; j < TN; j++) {
                float v = vals[j];
                vals[j] = 0.5f * v * (1.0f + erff(v * 0.70710678118654752f));
            }
        }
        *(float4*)(out + ro)     = make_float4(vals[0], vals[1], vals[2], vals[3]);
        *(float4*)(out + ro + 4) = make_float4(vals[4], vals[5], vals[6], vals[7]);
    }
}

// ---------------- launcher --------------------------------------------------
extern "C" void kernel_launch(void* const* d_in, const int* in_sizes, int n_in,
                              void* d_out, int out_size) {
    const float* x       = (const float*)d_in[0];
    const float* decay   = (const float*)d_in[1];
    const float* W_out   = (const float*)d_in[2];
    const float* b_out   = (const float*)d_in[3];
    const float* conv_w  = (const float*)d_in[4];
    const float* conv_b  = (const float*)d_in[5];
    const float* ln1_g   = (const float*)d_in[6];
    const float* ln1_b   = (const float*)d_in[7];
    const float* ln2_g   = (const float*)d_in[8];
    const float* ln2_b   = (const float*)d_in[9];
    const float* W1      = (const float*)d_in[10];
    const float* b1      = (const float*)d_in[11];
    const float* W2      = (const float*)d_in[12];
    const float* b2      = (const float*)d_in[13];
    float* out = (float*)d_out;

    float *xn, *ss, *x1, *h, *lend, *carry;
    cudaGetSymbolAddress((void**)&xn,    g_xn);
    cudaGetSymbolAddress((void**)&ss,    g_ss);
    cudaGetSymbolAddress((void**)&x1,    g_x1);
    cudaGetSymbolAddress((void**)&h,     g_h);
    cudaGetSymbolAddress((void**)&lend,  g_lend);
    cudaGetSymbolAddress((void**)&carry, g_carry);

    // 1) xn = LN1(x)
    ln_kernel<<<NTOK, 128>>>(x, ln1_g, ln1_b, xn);

    // 2) retention scan (chunked)
    scan_partial<<<(Bz * CH * Dz) / 256, 256>>>(xn, decay, lend);
    scan_carry<<<(Bz * Dz) / 256, 256>>>(lend, decay, carry);
    scan_final<<<(Bz * CH * Dz) / 256, 256>>>(xn, decay, carry, ss);

    // 3) x1 = x + ss @ W_out^T + b_out
    gemm_nt<0><<<dim3(Dz / BN, NTOK / BM), 256>>>(ss, W_out, b_out, NTOK, Dz, Dz, x, x1);

    // 4) x1 += depthwise_conv(xn) + conv_b
    conv_add<<<((size_t)NTOK * Dz) / 256, 256>>>(xn, conv_w, conv_b, x1);

    // 5) xn = LN2(x1)
    ln_kernel<<<NTOK, 128>>>(x1, ln2_g, ln2_b, xn);

    // 6) h = gelu(xn @ W1^T + b1)
    gemm_nt<1><<<dim3(HIDz / BN, NTOK / BM), 256>>>(xn, W1, b1, NTOK, HIDz, Dz, nullptr, h);

    // 7) out = x1 + h @ W2^T + b2
    gemm_nt<0><<<dim3(Dz / BN, NTOK / BM), 256>>>(h, W2, b2, NTOK, Dz, HIDz, x1, out);
}

// round 4
// speedup vs baseline: 3.4851x; 3.4851x over previous
#include <cuda_runtime.h>
#include <cuda_bf16.h>
#include <math.h>
#include <stdint.h>
#include <stddef.h>

// Problem constants
#define Bz   8
#define Tz   4096
#define Dz   512
#define HIDz 1024
#define Kz   5
#define NTOK (Bz * Tz)          // 32768
#define CH   16                 // scan chunks
#define LCH  (Tz / CH)          // 256

// ---------------- scratch (static device globals; no runtime alloc) -------
__device__ float        g_xn  [(size_t)NTOK * Dz];   // LN1 output fp32
__device__ float        g_x1  [(size_t)NTOK * Dz];   // mid residual fp32
__device__ float        g_yloc[(size_t)NTOK * Dz];   // conv output fp32
__device__ __nv_bfloat16 g_ssb [(size_t)NTOK * Dz];  // retention states bf16
__device__ __nv_bfloat16 g_xn2b[(size_t)NTOK * Dz];  // LN2 output bf16
__device__ __nv_bfloat16 g_hb  [(size_t)NTOK * HIDz];// MLP hidden bf16
__device__ float        g_lend [Bz * CH * Dz];
__device__ float        g_carry[Bz * CH * Dz];
__device__ __nv_bfloat16 g_woutb[Dz * Dz];
__device__ __nv_bfloat16 g_w1b [HIDz * Dz];
__device__ __nv_bfloat16 g_w2b [Dz * HIDz];

// =================== small helpers ===================
__device__ __forceinline__ uint32_t smem_u32(const void* p) {
    uint32_t a;
    asm("{ .reg .u64 t; cvta.to.shared.u64 t, %1; cvt.u32.u64 %0, t; }"
        : "=r"(a) : "l"(p));
    return a;
}

// =================== layernorm (fp32 or bf16 out) ===================
template<int BF16OUT>
__global__ void ln_kernel(const float* __restrict__ xin,
                          const float* __restrict__ gam,
                          const float* __restrict__ bet,
                          void* __restrict__ outp) {
    int tok = blockIdx.x;
    const float4* xr = (const float4*)(xin + (size_t)tok * Dz);
    float4 v = xr[threadIdx.x];
    float s  = v.x + v.y + v.z + v.w;
    float s2 = v.x*v.x + v.y*v.y + v.z*v.z + v.w*v.w;

    __shared__ float sh[8];
    #pragma unroll
    for (int o = 16; o > 0; o >>= 1) {
        s  += __shfl_down_sync(0xffffffffu, s,  o);
        s2 += __shfl_down_sync(0xffffffffu, s2, o);
    }
    int w = threadIdx.x >> 5;
    if ((threadIdx.x & 31) == 0) { sh[w] = s; sh[4 + w] = s2; }
    __syncthreads();
    __shared__ float mu_s, inv_s;
    if (threadIdx.x == 0) {
        float ts  = sh[0] + sh[1] + sh[2] + sh[3];
        float ts2 = sh[4] + sh[5] + sh[6] + sh[7];
        float mu  = ts * (1.0f / Dz);
        float var = ts2 * (1.0f / Dz) - mu * mu;
        mu_s  = mu;
        inv_s = rsqrtf(var + 1e-5f);
    }
    __syncthreads();
    float mu = mu_s, inv = inv_s;
    float4 gg = ((const float4*)gam)[threadIdx.x];
    float4 bb = ((const float4*)bet)[threadIdx.x];
    float o0 = (v.x - mu) * inv * gg.x + bb.x;
    float o1 = (v.y - mu) * inv * gg.y + bb.y;
    float o2 = (v.z - mu) * inv * gg.z + bb.z;
    float o3 = (v.w - mu) * inv * gg.w + bb.w;
    if (BF16OUT) {
        __nv_bfloat162* ob = (__nv_bfloat162*)((__nv_bfloat16*)outp + (size_t)tok * Dz);
        ob[threadIdx.x * 2 + 0] = __floats2bfloat162_rn(o0, o1);
        ob[threadIdx.x * 2 + 1] = __floats2bfloat162_rn(o2, o3);
    } else {
        ((float4*)((float*)outp + (size_t)tok * Dz))[threadIdx.x] =
            make_float4(o0, o1, o2, o3);
    }
}

// =================== chunked linear scan ===================
__global__ void scan_partial(const float* __restrict__ xn,
                             const float* __restrict__ decay,
                             float* __restrict__ lend) {
    int idx = blockIdx.x * blockDim.x + threadIdx.x;
    int d = idx & (Dz - 1);
    int c = (idx >> 9) & (CH - 1);
    int b = idx >> 13;
    float a  = 1.0f / (1.0f + expf(-decay[d]));
    float na = 1.0f - a;
    const float* p = xn + ((size_t)(b * Tz + c * LCH)) * Dz + d;
    float s = 0.0f;
    #pragma unroll 8
    for (int t = 0; t < LCH; t++) s = a * s + na * p[(size_t)t * Dz];
    lend[idx] = s;
}

__global__ void scan_carry(const float* __restrict__ lend,
                           const float* __restrict__ decay,
                           float* __restrict__ carry) {
    int idx = blockIdx.x * blockDim.x + threadIdx.x;   // B*Dz threads
    int d = idx & (Dz - 1);
    int b = idx >> 9;
    float a  = 1.0f / (1.0f + expf(-decay[d]));
    float aL = powf(a, (float)LCH);
    float s = 0.0f;
    #pragma unroll
    for (int c = 0; c < CH; c++) {
        int e = (b * CH + c) * Dz + d;
        carry[e] = s;
        s = aL * s + lend[e];
    }
}

// fused: final scan pass (bf16 ss out) + depthwise conv K=5 (fp32 yloc out)
__global__ void scan_final_fused(const float* __restrict__ xn,
                                 const float* __restrict__ decay,
                                 const float* __restrict__ carry,
                                 const float* __restrict__ cw,
                                 const float* __restrict__ cb,
                                 __nv_bfloat16* __restrict__ ssb,
                                 float* __restrict__ yloc) {
    int idx = blockIdx.x * blockDim.x + threadIdx.x;
    int d = idx & (Dz - 1);
    int c = (idx >> 9) & (CH - 1);
    int b = idx >> 13;
    float a  = 1.0f / (1.0f + expf(-decay[d]));
    float na = 1.0f - a;
    float w0 = cw[d * Kz + 0], w1 = cw[d * Kz + 1], w2 = cw[d * Kz + 2];
    float w3 = cw[d * Kz + 3], w4 = cw[d * Kz + 4];
    float bb = cb[d];
    int t0 = c * LCH;
    size_t base = ((size_t)(b * Tz + t0)) * Dz + d;
    const float* p = xn + base;
    float xm2 = (t0 >= 2)       ? p[-2 * (ptrdiff_t)Dz] : 0.0f;
    float xm1 = (t0 >= 1)       ? p[-1 * (ptrdiff_t)Dz] : 0.0f;
    float x0  = p[0];
    float x1v = p[(size_t)Dz];
    float s = carry[idx];
    #pragma unroll 4
    for (int t = 0; t < LCH; t++) {
        int tg = t0 + t;
        float x2 = (tg + 2 < Tz) ? p[(size_t)(t + 2) * Dz] : 0.0f;
        s = a * s + na * x0;
        ssb[base + (size_t)t * Dz] = __float2bfloat16(s);
        yloc[base + (size_t)t * Dz] =
            bb + w0 * xm2 + w1 * xm1 + w2 * x0 + w3 * x1v + w4 * x2;
        xm2 = xm1; xm1 = x0; x0 = x1v; x1v = x2;
    }
}

// =================== weight fp32 -> bf16 ===================
__global__ void f2bf(const float* __restrict__ w, __nv_bfloat16* __restrict__ o, int n) {
    int i = blockIdx.x * blockDim.x + threadIdx.x;
    if (i < n) o[i] = __float2bfloat16(w[i]);
}

// =================== mma.sync bf16 GEMM ===================
// C[M,N] = A[M,K] * W[N,K]^T.  Both operands K-major.
// EPI 0: out fp32 = acc + bias + res1
// EPI 1: out bf16 = gelu(acc + bias)
// EPI 2: out fp32 = acc + bias + res1 + res2
#define RSTRIDE 144u                       // smem bytes per row (128 data + 16 pad)
#define TILE_BYTES (128u * RSTRIDE)        // 18432 per operand per stage
#define STAGE_B (2u * TILE_BYTES)          // 36864
#define NSTAGE 3
#define GEMM_SMEM (NSTAGE * STAGE_B)       // 110592

__device__ __forceinline__ void ldm_x4(uint32_t* r, uint32_t addr) {
    asm volatile("ldmatrix.sync.aligned.m8n8.x4.shared.b16 {%0,%1,%2,%3}, [%4];"
                 : "=r"(r[0]), "=r"(r[1]), "=r"(r[2]), "=r"(r[3]) : "r"(addr));
}
__device__ __forceinline__ void mma16816(float* c, const uint32_t* a, const uint32_t* b) {
    asm volatile(
        "mma.sync.aligned.m16n8k16.row.col.f32.bf16.bf16.f32 "
        "{%0,%1,%2,%3}, {%4,%5,%6,%7}, {%8,%9}, {%0,%1,%2,%3};"
        : "+f"(c[0]), "+f"(c[1]), "+f"(c[2]), "+f"(c[3])
        : "r"(a[0]), "r"(a[1]), "r"(a[2]), "r"(a[3]), "r"(b[0]), "r"(b[1]));
}

template<int EPI>
__global__ void __launch_bounds__(256, 1)
gemm_mma(const __nv_bfloat16* __restrict__ A, const __nv_bfloat16* __restrict__ W,
         const float* __restrict__ bias, int M, int N, int Kd,
         const float* __restrict__ res1, const float* __restrict__ res2,
         void* __restrict__ outp)
{
    extern __shared__ __align__(128) char smem[];
    const uint32_t sb = smem_u32(smem);
    const int tid  = threadIdx.x;
    const int lane = tid & 31;
    const int wid  = tid >> 5;
    const int warp_m = wid >> 2;        // 0..1
    const int warp_n = wid & 3;         // 0..3
    const int NK = Kd >> 6;             // K / 64
    const int NB = N >> 7;
    const int bn = blockIdx.x % NB;
    const int bm = blockIdx.x / NB;
    const size_t Kb = (size_t)Kd * 2;   // row bytes in gmem

    const char* At = (const char*)A + ((size_t)bm << 7) * Kb;
    const char* Wt = (const char*)W + ((size_t)bn << 7) * Kb;

    // ---- async load of one 128x64 k-slab for both operands ----
    #define LOAD_STAGE(LS) do {                                               \
        uint32_t bufa = sb + (uint32_t)((LS) % NSTAGE) * STAGE_B;             \
        uint32_t bufw = bufa + TILE_BYTES;                                    \
        size_t kb = (size_t)(LS) * 128;                                       \
        _Pragma("unroll")                                                     \
        for (int i = 0; i < 4; i++) {                                         \
            int idx = (i << 8) + tid;                                         \
            uint32_t r = (uint32_t)(idx >> 3);                                \
            uint32_t j = (uint32_t)(idx & 7) << 4;                            \
            uint32_t so = r * RSTRIDE + j;                                    \
            asm volatile("cp.async.cg.shared.global [%0], [%1], 16;"          \
                :: "r"(bufa + so), "l"(At + (size_t)r * Kb + kb + j) : "memory"); \
            asm volatile("cp.async.cg.shared.global [%0], [%1], 16;"          \
                :: "r"(bufw + so), "l"(Wt + (size_t)r * Kb + kb + j) : "memory"); \
        }                                                                     \
    } while (0)

    float acc[4][4][4];
    #pragma unroll
    for (int i = 0; i < 4; i++)
        #pragma unroll
        for (int j = 0; j < 4; j++)
            #pragma unroll
            for (int r = 0; r < 4; r++) acc[i][j][r] = 0.0f;

    LOAD_STAGE(0);
    asm volatile("cp.async.commit_group;" ::: "memory");
    LOAD_STAGE(1);
    asm volatile("cp.async.commit_group;" ::: "memory");

    // per-lane ldmatrix row/col offsets
    const uint32_t lrow = (uint32_t)(lane & 15);
    const uint32_t lcol = (uint32_t)(lane & 16);   // +16B for k+8 half

    for (int kt = 0; kt < NK; kt++) {
        asm volatile("cp.async.wait_group 1;" ::: "memory");
        __syncthreads();

        if (kt + 2 < NK) LOAD_STAGE(kt + 2);
        asm volatile("cp.async.commit_group;" ::: "memory");

        uint32_t bufa = sb + (uint32_t)(kt % NSTAGE) * STAGE_B;
        uint32_t bufw = bufa + TILE_BYTES;
        uint32_t abase = bufa + (uint32_t)(warp_m * 64) * RSTRIDE + lrow * RSTRIDE + lcol;
        uint32_t wbase = bufw + (uint32_t)(warp_n * 32) * RSTRIDE + lrow * RSTRIDE + lcol;

        #pragma unroll
        for (int ks = 0; ks < 4; ks++) {
            uint32_t kb2 = (uint32_t)ks * 32;
            uint32_t af[4][4];
            #pragma unroll
            for (int im = 0; im < 4; im++)
                ldm_x4(af[im], abase + (uint32_t)(im * 16) * RSTRIDE + kb2);
            uint32_t bf[4][2];
            #pragma unroll
            for (int half = 0; half < 2; half++) {
                uint32_t t[4];
                ldm_x4(t, wbase + (uint32_t)(half * 16) * RSTRIDE + kb2);
                bf[half * 2 + 0][0] = t[0]; bf[half * 2 + 0][1] = t[2];
                bf[half * 2 + 1][0] = t[1]; bf[half * 2 + 1][1] = t[3];
            }
            #pragma unroll
            for (int im = 0; im < 4; im++)
                #pragma unroll
                for (int j = 0; j < 4; j++)
                    mma16816(acc[im][j], af[im], bf[j]);
        }
        __syncthreads();
    }
    #undef LOAD_STAGE

    // ---- epilogue ----
    const int g   = lane >> 2;
    const int tig = lane & 3;
    #pragma unroll
    for (int im = 0; im < 4; im++) {
        int gm = (bm << 7) + warp_m * 64 + im * 16 + g;
        #pragma unroll
        for (int j = 0; j < 4; j++) {
            int gn = (bn << 7) + warp_n * 32 + j * 8 + tig * 2;
            float bv0 = __ldg(&bias[gn]);
            float bv1 = __ldg(&bias[gn + 1]);
            #pragma unroll
            for (int half = 0; half < 2; half++) {
                int row = gm + half * 8;
                size_t off = (size_t)row * N + gn;
                float v0 = acc[im][j][half * 2 + 0] + bv0;
                float v1 = acc[im][j][half * 2 + 1] + bv1;
                if (EPI == 0) {
                    float2 r = *(const float2*)(res1 + off);
                    *(float2*)((float*)outp + off) = make_float2(v0 + r.x, v1 + r.y);
                } else if (EPI == 2) {
                    float2 r1 = *(const float2*)(res1 + off);
                    float2 r2 = *(const float2*)(res2 + off);
                    *(float2*)((float*)outp + off) =
                        make_float2(v0 + r1.x + r2.x, v1 + r1.y + r2.y);
                } else {
                    float g0 = 0.5f * v0 * (1.0f + erff(v0 * 0.70710678118654752f));
                    float g1 = 0.5f * v1 * (1.0f + erff(v1 * 0.70710678118654752f));
                    *(__nv_bfloat162*)((__nv_bfloat16*)outp + off) =
                        __floats2bfloat162_rn(g0, g1);
                }
            }
        }
    }
}

// =================== launcher ===================
extern "C" void kernel_launch(void* const* d_in, const int* in_sizes, int n_in,
                              void* d_out, int out_size) {
    const float* x       = (const float*)d_in[0];
    const float* decay   = (const float*)d_in[1];
    const float* W_out   = (const float*)d_in[2];
    const float* b_out   = (const float*)d_in[3];
    const float* conv_w  = (const float*)d_in[4];
    const float* conv_b  = (const float*)d_in[5];
    const float* ln1_g   = (const float*)d_in[6];
    const float* ln1_b   = (const float*)d_in[7];
    const float* ln2_g   = (const float*)d_in[8];
    const float* ln2_b   = (const float*)d_in[9];
    const float* W1      = (const float*)d_in[10];
    const float* b1      = (const float*)d_in[11];
    const float* W2      = (const float*)d_in[12];
    const float* b2      = (const float*)d_in[13];
    float* out = (float*)d_out;

    float *xn, *x1, *yloc, *lend, *carry;
    __nv_bfloat16 *ssb, *xn2b, *hb, *woutb, *w1b, *w2b;
    cudaGetSymbolAddress((void**)&xn,    g_xn);
    cudaGetSymbolAddress((void**)&x1,    g_x1);
    cudaGetSymbolAddress((void**)&yloc,  g_yloc);
    cudaGetSymbolAddress((void**)&lend,  g_lend);
    cudaGetSymbolAddress((void**)&carry, g_carry);
    cudaGetSymbolAddress((void**)&ssb,   g_ssb);
    cudaGetSymbolAddress((void**)&xn2b,  g_xn2b);
    cudaGetSymbolAddress((void**)&hb,    g_hb);
    cudaGetSymbolAddress((void**)&woutb, g_woutb);
    cudaGetSymbolAddress((void**)&w1b,   g_w1b);
    cudaGetSymbolAddress((void**)&w2b,   g_w2b);

    cudaFuncSetAttribute(gemm_mma<0>, cudaFuncAttributeMaxDynamicSharedMemorySize, GEMM_SMEM);
    cudaFuncSetAttribute(gemm_mma<1>, cudaFuncAttributeMaxDynamicSharedMemorySize, GEMM_SMEM);
    cudaFuncSetAttribute(gemm_mma<2>, cudaFuncAttributeMaxDynamicSharedMemorySize, GEMM_SMEM);

    // weight conversion (cheap, deterministic each call)
    f2bf<<<(Dz * Dz + 255) / 256, 256>>>(W_out, woutb, Dz * Dz);
    f2bf<<<(HIDz * Dz + 255) / 256, 256>>>(W1, w1b, HIDz * Dz);
    f2bf<<<(Dz * HIDz + 255) / 256, 256>>>(W2, w2b, Dz * HIDz);

    // 1) xn = LN1(x)  (fp32)
    ln_kernel<0><<<NTOK, 128>>>(x, ln1_g, ln1_b, xn);

    // 2) retention scan (chunked) + fused depthwise conv
    scan_partial<<<(Bz * CH * Dz) / 256, 256>>>(xn, decay, lend);
    scan_carry<<<(Bz * Dz) / 256, 256>>>(lend, decay, carry);
    scan_final_fused<<<(Bz * CH * Dz) / 256, 256>>>(xn, decay, carry,
                                                    conv_w, conv_b, ssb, yloc);

    // 3) x1 = x + yloc + ss @ W_out^T + b_out
    gemm_mma<2><<<(NTOK / 128) * (Dz / 128), 256, GEMM_SMEM>>>(
        ssb, woutb, b_out, NTOK, Dz, Dz, x, yloc, x1);

    // 4) xn2 = LN2(x1)  (bf16)
    ln_kernel<1><<<NTOK, 128>>>(x1, ln2_g, ln2_b, xn2b);

    // 5) h = gelu(xn2 @ W1^T + b1)  (bf16 out)
    gemm_mma<1><<<(NTOK / 128) * (HIDz / 128), 256, GEMM_SMEM>>>(
        xn2b, w1b, b1, NTOK, HIDz, Dz, nullptr, nullptr, hb);

    // 6) out = x1 + h @ W2^T + b2
    gemm_mma<0><<<(NTOK / 128) * (Dz / 128), 256, GEMM_SMEM>>>(
        hb, w2b, b2, NTOK, Dz, HIDz, x1, nullptr, out);
}

// round 5
// speedup vs baseline: 3.8431x; 1.1027x over previous
#include <cuda_runtime.h>
#include <cuda_fp16.h>
#include <math.h>
#include <stdint.h>
#include <stddef.h>

// Problem constants
#define Bz   8
#define Tz   4096
#define Dz   512
#define HIDz 1024
#define Kz   5
#define NTOK (Bz * Tz)          // 32768
#define CH   16                 // scan chunks
#define LCH  (Tz / CH)          // 256

// ---------------- scratch (static device globals; no runtime alloc) -------
__device__ __half g_xnh [(size_t)NTOK * Dz];   // LN1 output fp16
__device__ float  g_x1  [(size_t)NTOK * Dz];   // mid residual fp32
__device__ float  g_yloc[(size_t)NTOK * Dz];   // conv output fp32
__device__ __half g_ssh [(size_t)NTOK * Dz];   // retention states fp16
__device__ __half g_xn2h[(size_t)NTOK * Dz];   // LN2 output fp16
__device__ __half g_hh  [(size_t)NTOK * HIDz]; // MLP hidden fp16
__device__ float  g_lend [Bz * CH * Dz];
__device__ float  g_carry[Bz * CH * Dz];
__device__ __half g_wouth[Dz * Dz];
__device__ __half g_w1h [HIDz * Dz];
__device__ __half g_w2h [Dz * HIDz];

// =================== small helpers ===================
__device__ __forceinline__ uint32_t smem_u32(const void* p) {
    uint32_t a;
    asm("{ .reg .u64 t; cvta.to.shared.u64 t, %1; cvt.u32.u64 %0, t; }"
        : "=r"(a) : "l"(p));
    return a;
}

// =================== layernorm: one warp per token, fp16 out ==============
__global__ void ln_kernel(const float* __restrict__ xin,
                          const float* __restrict__ gam,
                          const float* __restrict__ bet,
                          __half* __restrict__ outp) {
    int gw   = (blockIdx.x * blockDim.x + threadIdx.x) >> 5;  // token
    int lane = threadIdx.x & 31;
    const float4* xr = (const float4*)(xin + (size_t)gw * Dz);

    float4 v[4];
    #pragma unroll
    for (int i = 0; i < 4; i++) v[i] = xr[lane + 32 * i];

    float s = 0.0f, s2 = 0.0f;
    #pragma unroll
    for (int i = 0; i < 4; i++) {
        s  += v[i].x + v[i].y + v[i].z + v[i].w;
        s2 += v[i].x*v[i].x + v[i].y*v[i].y + v[i].z*v[i].z + v[i].w*v[i].w;
    }
    #pragma unroll
    for (int o = 16; o > 0; o >>= 1) {
        s  += __shfl_xor_sync(0xffffffffu, s,  o);
        s2 += __shfl_xor_sync(0xffffffffu, s2, o);
    }
    float mu  = s * (1.0f / Dz);
    float var = s2 * (1.0f / Dz) - mu * mu;
    float inv = rsqrtf(var + 1e-5f);

    __half2* ob = (__half2*)(outp + (size_t)gw * Dz);
    #pragma unroll
    for (int i = 0; i < 4; i++) {
        int c = lane + 32 * i;
        float4 gg = ((const float4*)gam)[c];
        float4 bb = ((const float4*)bet)[c];
        float o0 = (v[i].x - mu) * inv * gg.x + bb.x;
        float o1 = (v[i].y - mu) * inv * gg.y + bb.y;
        float o2 = (v[i].z - mu) * inv * gg.z + bb.z;
        float o3 = (v[i].w - mu) * inv * gg.w + bb.w;
        ob[c * 2 + 0] = __floats2half2_rn(o0, o1);
        ob[c * 2 + 1] = __floats2half2_rn(o2, o3);
    }
}

// =================== chunked linear scan (fp16 in) ===================
__global__ void scan_partial(const __half* __restrict__ xn,
                             const float* __restrict__ decay,
                             float* __restrict__ lend) {
    int idx = blockIdx.x * blockDim.x + threadIdx.x;
    int d = idx & (Dz - 1);
    int c = (idx >> 9) & (CH - 1);
    int b = idx >> 13;
    float a  = 1.0f / (1.0f + expf(-decay[d]));
    float na = 1.0f - a;
    const __half* p = xn + ((size_t)(b * Tz + c * LCH)) * Dz + d;
    float s = 0.0f;
    #pragma unroll 8
    for (int t = 0; t < LCH; t++) s = a * s + na * __half2float(p[(size_t)t * Dz]);
    lend[idx] = s;
}

__global__ void scan_carry(const float* __restrict__ lend,
                           const float* __restrict__ decay,
                           float* __restrict__ carry) {
    int idx = blockIdx.x * blockDim.x + threadIdx.x;   // B*Dz threads
    int d = idx & (Dz - 1);
    int b = idx >> 9;
    float a  = 1.0f / (1.0f + expf(-decay[d]));
    float aL = powf(a, (float)LCH);
    float s = 0.0f;
    #pragma unroll
    for (int c = 0; c < CH; c++) {
        int e = (b * CH + c) * Dz + d;
        carry[e] = s;
        s = aL * s + lend[e];
    }
}

// fused: final scan pass (fp16 ss out) + depthwise conv K=5 (fp32 yloc out)
__global__ void scan_final_fused(const __half* __restrict__ xn,
                                 const float* __restrict__ decay,
                                 const float* __restrict__ carry,
                                 const float* __restrict__ cw,
                                 const float* __restrict__ cb,
                                 __half* __restrict__ ssh,
                                 float* __restrict__ yloc) {
    int idx = blockIdx.x * blockDim.x + threadIdx.x;
    int d = idx & (Dz - 1);
    int c = (idx >> 9) & (CH - 1);
    int b = idx >> 13;
    float a  = 1.0f / (1.0f + expf(-decay[d]));
    float na = 1.0f - a;
    float w0 = cw[d * Kz + 0], w1 = cw[d * Kz + 1], w2 = cw[d * Kz + 2];
    float w3 = cw[d * Kz + 3], w4 = cw[d * Kz + 4];
    float bb = cb[d];
    int t0 = c * LCH;
    size_t base = ((size_t)(b * Tz + t0)) * Dz + d;
    const __half* p = xn + base;
    float xm2 = (t0 >= 2) ? __half2float(p[-2 * (ptrdiff_t)Dz]) : 0.0f;
    float xm1 = (t0 >= 1) ? __half2float(p[-1 * (ptrdiff_t)Dz]) : 0.0f;
    float x0  = __half2float(p[0]);
    float x1v = __half2float(p[(size_t)Dz]);
    float s = carry[idx];
    #pragma unroll 4
    for (int t = 0; t < LCH; t++) {
        int tg = t0 + t;
        float x2 = (tg + 2 < Tz) ? __half2float(p[(size_t)(t + 2) * Dz]) : 0.0f;
        s = a * s + na * x0;
        ssh[base + (size_t)t * Dz] = __float2half(s);
        yloc[base + (size_t)t * Dz] =
            bb + w0 * xm2 + w1 * xm1 + w2 * x0 + w3 * x1v + w4 * x2;
        xm2 = xm1; xm1 = x0; x0 = x1v; x1v = x2;
    }
}

// =================== weights fp32 -> fp16 (single launch) ===================
#define N0 (Dz * Dz)
#define N1 (HIDz * Dz)
#define N2 (Dz * HIDz)
__global__ void wconv(const float* __restrict__ w0, const float* __restrict__ w1,
                      const float* __restrict__ w2,
                      __half* __restrict__ o0, __half* __restrict__ o1,
                      __half* __restrict__ o2) {
    int i = blockIdx.x * blockDim.x + threadIdx.x;
    if (i < N0)                o0[i]           = __float2half(w0[i]);
    else if (i < N0 + N1)      o1[i - N0]      = __float2half(w1[i - N0]);
    else if (i < N0 + N1 + N2) o2[i - N0 - N1] = __float2half(w2[i - N0 - N1]);
}

// =================== mma.sync fp16 GEMM ===================
// C[M,N] = A[M,K] * W[N,K]^T.  Both operands K-major.
// EPI 0: out fp32 = acc + bias + res1
// EPI 1: out fp16 = gelu(acc + bias)
// EPI 2: out fp32 = acc + bias + res1 + res2
#define RSTRIDE 144u                       // smem bytes per row (128 data + 16 pad)
#define TILE_BYTES (128u * RSTRIDE)        // 18432 per operand per stage
#define STAGE_B (2u * TILE_BYTES)          // 36864
#define NSTAGE 3
#define GEMM_SMEM (NSTAGE * STAGE_B)       // 110592

__device__ __forceinline__ void ldm_x4(uint32_t* r, uint32_t addr) {
    asm volatile("ldmatrix.sync.aligned.m8n8.x4.shared.b16 {%0,%1,%2,%3}, [%4];"
                 : "=r"(r[0]), "=r"(r[1]), "=r"(r[2]), "=r"(r[3]) : "r"(addr));
}
__device__ __forceinline__ void mma16816(float* c, const uint32_t* a, const uint32_t* b) {
    asm volatile(
        "mma.sync.aligned.m16n8k16.row.col.f32.f16.f16.f32 "
        "{%0,%1,%2,%3}, {%4,%5,%6,%7}, {%8,%9}, {%0,%1,%2,%3};"
        : "+f"(c[0]), "+f"(c[1]), "+f"(c[2]), "+f"(c[3])
        : "r"(a[0]), "r"(a[1]), "r"(a[2]), "r"(a[3]), "r"(b[0]), "r"(b[1]));
}

template<int EPI>
__global__ void __launch_bounds__(256, 1)
gemm_mma(const __half* __restrict__ A, const __half* __restrict__ W,
         const float* __restrict__ bias, int M, int N, int Kd,
         const float* __restrict__ res1, const float* __restrict__ res2,
         void* __restrict__ outp)
{
    extern __shared__ __align__(128) char smem[];
    const uint32_t sb = smem_u32(smem);
    const int tid  = threadIdx.x;
    const int lane = tid & 31;
    const int wid  = tid >> 5;
    const int warp_m = wid >> 2;        // 0..1
    const int warp_n = wid & 3;         // 0..3
    const int NK = Kd >> 6;             // K / 64
    const int NB = N >> 7;
    const int bn = blockIdx.x % NB;
    const int bm = blockIdx.x / NB;
    const size_t Kb = (size_t)Kd * 2;   // row bytes in gmem

    const char* At = (const char*)A + ((size_t)bm << 7) * Kb;
    const char* Wt = (const char*)W + ((size_t)bn << 7) * Kb;

    // ---- async load of one 128x64 k-slab for both operands ----
    #define LOAD_STAGE(LS) do {                                               \
        uint32_t bufa = sb + (uint32_t)((LS) % NSTAGE) * STAGE_B;             \
        uint32_t bufw = bufa + TILE_BYTES;                                    \
        size_t kb = (size_t)(LS) * 128;                                       \
        _Pragma("unroll")                                                     \
        for (int i = 0; i < 4; i++) {                                         \
            int idx = (i << 8) + tid;                                         \
            uint32_t r = (uint32_t)(idx >> 3);                                \
            uint32_t j = (uint32_t)(idx & 7) << 4;                            \
            uint32_t so = r * RSTRIDE + j;                                    \
            asm volatile("cp.async.cg.shared.global [%0], [%1], 16;"          \
                :: "r"(bufa + so), "l"(At + (size_t)r * Kb + kb + j) : "memory"); \
            asm volatile("cp.async.cg.shared.global [%0], [%1], 16;"          \
                :: "r"(bufw + so), "l"(Wt + (size_t)r * Kb + kb + j) : "memory"); \
        }                                                                     \
    } while (0)

    float acc[4][4][4];
    #pragma unroll
    for (int i = 0; i < 4; i++)
        #pragma unroll
        for (int j = 0; j < 4; j++)
            #pragma unroll
            for (int r = 0; r < 4; r++) acc[i][j][r] = 0.0f;

    LOAD_STAGE(0);
    asm volatile("cp.async.commit_group;" ::: "memory");
    LOAD_STAGE(1);
    asm volatile("cp.async.commit_group;" ::: "memory");

    // per-lane ldmatrix row/col offsets
    const uint32_t lrow = (uint32_t)(lane & 15);
    const uint32_t lcol = (uint32_t)(lane & 16);   // +16B for k+8 half

    for (int kt = 0; kt < NK; kt++) {
        asm volatile("cp.async.wait_group 1;" ::: "memory");
        __syncthreads();

        if (kt + 2 < NK) LOAD_STAGE(kt + 2);
        asm volatile("cp.async.commit_group;" ::: "memory");

        uint32_t bufa = sb + (uint32_t)(kt % NSTAGE) * STAGE_B;
        uint32_t bufw = bufa + TILE_BYTES;
        uint32_t abase = bufa + (uint32_t)(warp_m * 64) * RSTRIDE + lrow * RSTRIDE + lcol;
        uint32_t wbase = bufw + (uint32_t)(warp_n * 32) * RSTRIDE + lrow * RSTRIDE + lcol;

        #pragma unroll
        for (int ks = 0; ks < 4; ks++) {
            uint32_t kb2 = (uint32_t)ks * 32;
            uint32_t af[4][4];
            #pragma unroll
            for (int im = 0; im < 4; im++)
                ldm_x4(af[im], abase + (uint32_t)(im * 16) * RSTRIDE + kb2);
            uint32_t bf[4][2];
            #pragma unroll
            for (int half = 0; half < 2; half++) {
                uint32_t t[4];
                ldm_x4(t, wbase + (uint32_t)(half * 16) * RSTRIDE + kb2);
                bf[half * 2 + 0][0] = t[0]; bf[half * 2 + 0][1] = t[2];
                bf[half * 2 + 1][0] = t[1]; bf[half * 2 + 1][1] = t[3];
            }
            #pragma unroll
            for (int im = 0; im < 4; im++)
                #pragma unroll
                for (int j = 0; j < 4; j++)
                    mma16816(acc[im][j], af[im], bf[j]);
        }
        // NOTE: no bottom barrier needed — the top-of-loop __syncthreads()
        // (after wait_group) orders buffer reuse at 3 stages.
    }
    #undef LOAD_STAGE

    // ---- epilogue ----
    const int g   = lane >> 2;
    const int tig = lane & 3;
    #pragma unroll
    for (int im = 0; im < 4; im++) {
        int gm = (bm << 7) + warp_m * 64 + im * 16 + g;
        #pragma unroll
        for (int j = 0; j < 4; j++) {
            int gn = (bn << 7) + warp_n * 32 + j * 8 + tig * 2;
            float bv0 = __ldg(&bias[gn]);
            float bv1 = __ldg(&bias[gn + 1]);
            #pragma unroll
            for (int half = 0; half < 2; half++) {
                int row = gm + half * 8;
                size_t off = (size_t)row * N + gn;
                float v0 = acc[im][j][half * 2 + 0] + bv0;
                float v1 = acc[im][j][half * 2 + 1] + bv1;
                if (EPI == 0) {
                    float2 r = *(const float2*)(res1 + off);
                    *(float2*)((float*)outp + off) = make_float2(v0 + r.x, v1 + r.y);
                } else if (EPI == 2) {
                    float2 r1 = *(const float2*)(res1 + off);
                    float2 r2 = *(const float2*)(res2 + off);
                    *(float2*)((float*)outp + off) =
                        make_float2(v0 + r1.x + r2.x, v1 + r1.y + r2.y);
                } else {
                    float g0 = 0.5f * v0 * (1.0f + erff(v0 * 0.70710678118654752f));
                    float g1 = 0.5f * v1 * (1.0f + erff(v1 * 0.70710678118654752f));
                    *(__half2*)((__half*)outp + off) = __floats2half2_rn(g0, g1);
                }
            }
        }
    }
}

// =================== launcher ===================
extern "C" void kernel_launch(void* const* d_in, const int* in_sizes, int n_in,
                              void* d_out, int out_size) {
    const float* x       = (const float*)d_in[0];
    const float* decay   = (const float*)d_in[1];
    const float* W_out   = (const float*)d_in[2];
    const float* b_out   = (const float*)d_in[3];
    const float* conv_w  = (const float*)d_in[4];
    const float* conv_b  = (const float*)d_in[5];
    const float* ln1_g   = (const float*)d_in[6];
    const float* ln1_b   = (const float*)d_in[7];
    const float* ln2_g   = (const float*)d_in[8];
    const float* ln2_b   = (const float*)d_in[9];
    const float* W1      = (const float*)d_in[10];
    const float* b1      = (const float*)d_in[11];
    const float* W2      = (const float*)d_in[12];
    const float* b2      = (const float*)d_in[13];
    float* out = (float*)d_out;

    float *x1, *yloc, *lend, *carry;
    __half *xnh, *ssh, *xn2h, *hh, *wouth, *w1h, *w2h;
    cudaGetSymbolAddress((void**)&xnh,   g_xnh);
    cudaGetSymbolAddress((void**)&x1,    g_x1);
    cudaGetSymbolAddress((void**)&yloc,  g_yloc);
    cudaGetSymbolAddress((void**)&lend,  g_lend);
    cudaGetSymbolAddress((void**)&carry, g_carry);
    cudaGetSymbolAddress((void**)&ssh,   g_ssh);
    cudaGetSymbolAddress((void**)&xn2h,  g_xn2h);
    cudaGetSymbolAddress((void**)&hh,    g_hh);
    cudaGetSymbolAddress((void**)&wouth, g_wouth);
    cudaGetSymbolAddress((void**)&w1h,   g_w1h);
    cudaGetSymbolAddress((void**)&w2h,   g_w2h);

    cudaFuncSetAttribute(gemm_mma<0>, cudaFuncAttributeMaxDynamicSharedMemorySize, GEMM_SMEM);
    cudaFuncSetAttribute(gemm_mma<1>, cudaFuncAttributeMaxDynamicSharedMemorySize, GEMM_SMEM);
    cudaFuncSetAttribute(gemm_mma<2>, cudaFuncAttributeMaxDynamicSharedMemorySize, GEMM_SMEM);

    // weight conversion (single launch)
    wconv<<<(N0 + N1 + N2 + 255) / 256, 256>>>(W_out, W1, W2, wouth, w1h, w2h);

    // 1) xn = LN1(x)  (fp16)
    ln_kernel<<<NTOK / 8, 256>>>(x, ln1_g, ln1_b, xnh);

    // 2) retention scan (chunked) + fused depthwise conv
    scan_partial<<<(Bz * CH * Dz) / 256, 256>>>(xnh, decay, lend);
    scan_carry<<<(Bz * Dz) / 256, 256>>>(lend, decay, carry);
    scan_final_fused<<<(Bz * CH * Dz) / 256, 256>>>(xnh, decay, carry,
                                                    conv_w, conv_b, ssh, yloc);

    // 3) x1 = x + yloc + ss @ W_out^T + b_out
    gemm_mma<2><<<(NTOK / 128) * (Dz / 128), 256, GEMM_SMEM>>>(
        ssh, wouth, b_out, NTOK, Dz, Dz, x, yloc, x1);

    // 4) xn2 = LN2(x1)  (fp16)
    ln_kernel<<<NTOK / 8, 256>>>(x1, ln2_g, ln2_b, xn2h);

    // 5) h = gelu(xn2 @ W1^T + b1)  (fp16 out)
    gemm_mma<1><<<(NTOK / 128) * (HIDz / 128), 256, GEMM_SMEM>>>(
        xn2h, w1h, b1, NTOK, HIDz, Dz, nullptr, nullptr, hh);

    // 6) out = x1 + h @ W2^T + b2
    gemm_mma<0><<<(NTOK / 128) * (Dz / 128), 256, GEMM_SMEM>>>(
        hh, w2h, b2, NTOK, Dz, HIDz, x1, nullptr, out);
}

// round 6
// speedup vs baseline: 3.9841x; 1.0367x over previous
#include <cuda_runtime.h>
#include <cuda_fp16.h>
#include <math.h>
#include <stdint.h>
#include <stddef.h>

// Problem constants
#define Bz   8
#define Tz   4096
#define Dz   512
#define HIDz 1024
#define Kz   5
#define NTOK (Bz * Tz)          // 32768
#define CH   16                 // scan chunks
#define LCH  (Tz / CH)          // 256

// ---------------- scratch (static device globals; no runtime alloc) -------
__device__ __half g_xnh [(size_t)NTOK * Dz];   // LN1 output fp16
__device__ float  g_x1  [(size_t)NTOK * Dz];   // mid residual fp32
__device__ float  g_yloc[(size_t)NTOK * Dz];   // conv output fp32
__device__ __half g_ssh [(size_t)NTOK * Dz];   // retention states fp16
__device__ __half g_xn2h[(size_t)NTOK * Dz];   // LN2 output fp16
__device__ __half g_hh  [(size_t)NTOK * HIDz]; // MLP hidden fp16
__device__ float  g_lend [Bz * CH * Dz];
__device__ float  g_carry[Bz * CH * Dz];
__device__ __half g_wouth[Dz * Dz];
__device__ __half g_w1h [HIDz * Dz];
__device__ __half g_w2h [Dz * HIDz];

// =================== small helpers ===================
__device__ __forceinline__ uint32_t smem_u32(const void* p) {
    uint32_t a;
    asm("{ .reg .u64 t; cvta.to.shared.u64 t, %1; cvt.u32.u64 %0, t; }"
        : "=r"(a) : "l"(p));
    return a;
}

// =================== layernorm: one warp per token, fp16 out ==============
__global__ void ln_kernel(const float* __restrict__ xin,
                          const float* __restrict__ gam,
                          const float* __restrict__ bet,
                          __half* __restrict__ outp) {
    int gw   = (blockIdx.x * blockDim.x + threadIdx.x) >> 5;  // token
    int lane = threadIdx.x & 31;
    const float4* xr = (const float4*)(xin + (size_t)gw * Dz);

    float4 v[4];
    #pragma unroll
    for (int i = 0; i < 4; i++) v[i] = xr[lane + 32 * i];

    float s = 0.0f, s2 = 0.0f;
    #pragma unroll
    for (int i = 0; i < 4; i++) {
        s  += v[i].x + v[i].y + v[i].z + v[i].w;
        s2 += v[i].x*v[i].x + v[i].y*v[i].y + v[i].z*v[i].z + v[i].w*v[i].w;
    }
    #pragma unroll
    for (int o = 16; o > 0; o >>= 1) {
        s  += __shfl_xor_sync(0xffffffffu, s,  o);
        s2 += __shfl_xor_sync(0xffffffffu, s2, o);
    }
    float mu  = s * (1.0f / Dz);
    float var = s2 * (1.0f / Dz) - mu * mu;
    float inv = rsqrtf(var + 1e-5f);

    __half2* ob = (__half2*)(outp + (size_t)gw * Dz);
    #pragma unroll
    for (int i = 0; i < 4; i++) {
        int c = lane + 32 * i;
        float4 gg = ((const float4*)gam)[c];
        float4 bb = ((const float4*)bet)[c];
        float o0 = (v[i].x - mu) * inv * gg.x + bb.x;
        float o1 = (v[i].y - mu) * inv * gg.y + bb.y;
        float o2 = (v[i].z - mu) * inv * gg.z + bb.z;
        float o3 = (v[i].w - mu) * inv * gg.w + bb.w;
        ob[c * 2 + 0] = __floats2half2_rn(o0, o1);
        ob[c * 2 + 1] = __floats2half2_rn(o2, o3);
    }
}

// =================== chunked linear scan (fp16 in) ===================
__global__ void scan_partial(const __half* __restrict__ xn,
                             const float* __restrict__ decay,
                             float* __restrict__ lend) {
    int idx = blockIdx.x * blockDim.x + threadIdx.x;
    int d = idx & (Dz - 1);
    int c = (idx >> 9) & (CH - 1);
    int b = idx >> 13;
    float a  = 1.0f / (1.0f + expf(-decay[d]));
    float na = 1.0f - a;
    const __half* p = xn + ((size_t)(b * Tz + c * LCH)) * Dz + d;
    float s = 0.0f;
    #pragma unroll 8
    for (int t = 0; t < LCH; t++) s = a * s + na * __half2float(p[(size_t)t * Dz]);
    lend[idx] = s;
}

__global__ void scan_carry(const float* __restrict__ lend,
                           const float* __restrict__ decay,
                           float* __restrict__ carry) {
    int idx = blockIdx.x * blockDim.x + threadIdx.x;   // B*Dz threads
    int d = idx & (Dz - 1);
    int b = idx >> 9;
    float a  = 1.0f / (1.0f + expf(-decay[d]));
    float aL = powf(a, (float)LCH);
    float s = 0.0f;
    #pragma unroll
    for (int c = 0; c < CH; c++) {
        int e = (b * CH + c) * Dz + d;
        carry[e] = s;
        s = aL * s + lend[e];
    }
}

// fused: final scan pass (fp16 ss out) + depthwise conv K=5 (fp32 yloc out)
__global__ void scan_final_fused(const __half* __restrict__ xn,
                                 const float* __restrict__ decay,
                                 const float* __restrict__ carry,
                                 const float* __restrict__ cw,
                                 const float* __restrict__ cb,
                                 __half* __restrict__ ssh,
                                 float* __restrict__ yloc) {
    int idx = blockIdx.x * blockDim.x + threadIdx.x;
    int d = idx & (Dz - 1);
    int c = (idx >> 9) & (CH - 1);
    int b = idx >> 13;
    float a  = 1.0f / (1.0f + expf(-decay[d]));
    float na = 1.0f - a;
    float w0 = cw[d * Kz + 0], w1 = cw[d * Kz + 1], w2 = cw[d * Kz + 2];
    float w3 = cw[d * Kz + 3], w4 = cw[d * Kz + 4];
    float bb = cb[d];
    int t0 = c * LCH;
    size_t base = ((size_t)(b * Tz + t0)) * Dz + d;
    const __half* p = xn + base;
    float xm2 = (t0 >= 2) ? __half2float(p[-2 * (ptrdiff_t)Dz]) : 0.0f;
    float xm1 = (t0 >= 1) ? __half2float(p[-1 * (ptrdiff_t)Dz]) : 0.0f;
    float x0  = __half2float(p[0]);
    float x1v = __half2float(p[(size_t)Dz]);
    float s = carry[idx];
    #pragma unroll 4
    for (int t = 0; t < LCH; t++) {
        int tg = t0 + t;
        float x2 = (tg + 2 < Tz) ? __half2float(p[(size_t)(t + 2) * Dz]) : 0.0f;
        s = a * s + na * x0;
        ssh[base + (size_t)t * Dz] = __float2half(s);
        yloc[base + (size_t)t * Dz] =
            bb + w0 * xm2 + w1 * xm1 + w2 * x0 + w3 * x1v + w4 * x2;
        xm2 = xm1; xm1 = x0; x0 = x1v; x1v = x2;
    }
}

// =================== weights fp32 -> fp16 (single launch) ===================
#define N0 (Dz * Dz)
#define N1 (HIDz * Dz)
#define N2 (Dz * HIDz)
__global__ void wconv(const float* __restrict__ w0, const float* __restrict__ w1,
                      const float* __restrict__ w2,
                      __half* __restrict__ o0, __half* __restrict__ o1,
                      __half* __restrict__ o2) {
    int i = blockIdx.x * blockDim.x + threadIdx.x;
    if (i < N0)                o0[i]           = __float2half(w0[i]);
    else if (i < N0 + N1)      o1[i - N0]      = __float2half(w1[i - N0]);
    else if (i < N0 + N1 + N2) o2[i - N0 - N1] = __float2half(w2[i - N0 - N1]);
}

// =================== mma.sync fp16 GEMM (BM=128, BN=256, BK=64) ============
// C[M,N] = A[M,K] * W[N,K]^T.  Both operands K-major.
// 8 warps in 2(M)x4(N), warp tile 64x64.
// EPI 0: out fp32 = acc + bias + res1
// EPI 1: out fp16 = gelu(acc + bias)
// EPI 2: out fp32 = acc + bias + res1 + res2
#define RSTRIDE 144u                       // smem bytes per row (128 data + 16 pad)
#define A_TILE_B (128u * RSTRIDE)          // 18432
#define W_TILE_B (256u * RSTRIDE)          // 36864
#define STAGE_B (A_TILE_B + W_TILE_B)      // 55296
#define NSTAGE 3
#define GEMM_SMEM (NSTAGE * STAGE_B)       // 165888

__device__ __forceinline__ void ldm_x4(uint32_t* r, uint32_t addr) {
    asm volatile("ldmatrix.sync.aligned.m8n8.x4.shared.b16 {%0,%1,%2,%3}, [%4];"
                 : "=r"(r[0]), "=r"(r[1]), "=r"(r[2]), "=r"(r[3]) : "r"(addr));
}
__device__ __forceinline__ void mma16816(float* c, const uint32_t* a, const uint32_t* b) {
    asm volatile(
        "mma.sync.aligned.m16n8k16.row.col.f32.f16.f16.f32 "
        "{%0,%1,%2,%3}, {%4,%5,%6,%7}, {%8,%9}, {%0,%1,%2,%3};"
        : "+f"(c[0]), "+f"(c[1]), "+f"(c[2]), "+f"(c[3])
        : "r"(a[0]), "r"(a[1]), "r"(a[2]), "r"(a[3]), "r"(b[0]), "r"(b[1]));
}

template<int EPI>
__global__ void __launch_bounds__(256, 1)
gemm_mma(const __half* __restrict__ A, const __half* __restrict__ W,
         const float* __restrict__ bias, int M, int N, int Kd,
         const float* __restrict__ res1, const float* __restrict__ res2,
         void* __restrict__ outp)
{
    extern __shared__ __align__(128) char smem[];
    const uint32_t sb = smem_u32(smem);
    const int tid  = threadIdx.x;
    const int lane = tid & 31;
    const int wid  = tid >> 5;
    const int warp_m = wid >> 2;        // 0..1  (x64 rows)
    const int warp_n = wid & 3;         // 0..3  (x64 cols)
    const int NK = Kd >> 6;             // K / 64
    const int NB = N >> 8;              // N / 256
    const int bn = blockIdx.x % NB;
    const int bm = blockIdx.x / NB;
    const size_t Kb = (size_t)Kd * 2;   // row bytes in gmem

    const char* At = (const char*)A + ((size_t)bm << 7) * Kb;
    const char* Wt = (const char*)W + ((size_t)bn << 8) * Kb;

    // ---- async load of one k-slab (A:128 rows, W:256 rows, 64 k each) ----
    #define LOAD_STAGE(LS) do {                                               \
        uint32_t bufa = sb + (uint32_t)((LS) % NSTAGE) * STAGE_B;             \
        uint32_t bufw = bufa + A_TILE_B;                                      \
        size_t kb = (size_t)(LS) * 128;                                       \
        _Pragma("unroll")                                                     \
        for (int i = 0; i < 4; i++) {                                         \
            int idx = (i << 8) + tid;                                         \
            uint32_t r = (uint32_t)(idx >> 3);                                \
            uint32_t j = (uint32_t)(idx & 7) << 4;                            \
            asm volatile("cp.async.cg.shared.global [%0], [%1], 16;"          \
                :: "r"(bufa + r * RSTRIDE + j),                               \
                   "l"(At + (size_t)r * Kb + kb + j) : "memory");             \
        }                                                                     \
        _Pragma("unroll")                                                     \
        for (int i = 0; i < 8; i++) {                                         \
            int idx = (i << 8) + tid;                                         \
            uint32_t r = (uint32_t)(idx >> 3);                                \
            uint32_t j = (uint32_t)(idx & 7) << 4;                            \
            asm volatile("cp.async.cg.shared.global [%0], [%1], 16;"          \
                :: "r"(bufw + r * RSTRIDE + j),                               \
                   "l"(Wt + (size_t)r * Kb + kb + j) : "memory");             \
        }                                                                     \
        asm volatile("cp.async.commit_group;" ::: "memory");                  \
    } while (0)

    float acc[4][8][4];
    #pragma unroll
    for (int i = 0; i < 4; i++)
        #pragma unroll
        for (int j = 0; j < 8; j++)
            #pragma unroll
            for (int r = 0; r < 4; r++) acc[i][j][r] = 0.0f;

    LOAD_STAGE(0);
    LOAD_STAGE(1);

    // per-lane ldmatrix row/col offsets
    const uint32_t lrow = (uint32_t)(lane & 15);
    const uint32_t lcol = (uint32_t)(lane & 16);   // +16B for k+8 half

    for (int kt = 0; kt < NK; kt++) {
        asm volatile("cp.async.wait_group 1;" ::: "memory");
        __syncthreads();

        if (kt + 2 < NK) {
            LOAD_STAGE(kt + 2);
        } else {
            asm volatile("cp.async.commit_group;" ::: "memory");
        }

        uint32_t bufa = sb + (uint32_t)(kt % NSTAGE) * STAGE_B;
        uint32_t bufw = bufa + A_TILE_B;
        uint32_t abase = bufa + ((uint32_t)(warp_m * 64) + lrow) * RSTRIDE + lcol;
        uint32_t wbase = bufw + ((uint32_t)(warp_n * 64) + lrow) * RSTRIDE + lcol;

        #pragma unroll
        for (int ks = 0; ks < 4; ks++) {
            uint32_t kb2 = (uint32_t)ks * 32;
            uint32_t af[4][4];
            #pragma unroll
            for (int im = 0; im < 4; im++)
                ldm_x4(af[im], abase + (uint32_t)(im * 16) * RSTRIDE + kb2);
            uint32_t bf[8][2];
            #pragma unroll
            for (int hn = 0; hn < 4; hn++) {
                uint32_t t[4];
                ldm_x4(t, wbase + (uint32_t)(hn * 16) * RSTRIDE + kb2);
                bf[hn * 2 + 0][0] = t[0]; bf[hn * 2 + 0][1] = t[2];
                bf[hn * 2 + 1][0] = t[1]; bf[hn * 2 + 1][1] = t[3];
            }
            #pragma unroll
            for (int im = 0; im < 4; im++)
                #pragma unroll
                for (int j = 0; j < 8; j++)
                    mma16816(acc[im][j], af[im], bf[j]);
        }
        // top-of-loop barrier (after wait_group) orders buffer reuse.
    }
    #undef LOAD_STAGE

    // ---- epilogue ----
    const int g   = lane >> 2;
    const int tig = lane & 3;
    #pragma unroll
    for (int im = 0; im < 4; im++) {
        int gm = (bm << 7) + warp_m * 64 + im * 16 + g;
        #pragma unroll
        for (int j = 0; j < 8; j++) {
            int gn = (bn << 8) + warp_n * 64 + j * 8 + tig * 2;
            float bv0 = __ldg(&bias[gn]);
            float bv1 = __ldg(&bias[gn + 1]);
            #pragma unroll
            for (int half = 0; half < 2; half++) {
                int row = gm + half * 8;
                size_t off = (size_t)row * N + gn;
                float v0 = acc[im][j][half * 2 + 0] + bv0;
                float v1 = acc[im][j][half * 2 + 1] + bv1;
                if (EPI == 0) {
                    float2 r = *(const float2*)(res1 + off);
                    *(float2*)((float*)outp + off) = make_float2(v0 + r.x, v1 + r.y);
                } else if (EPI == 2) {
                    float2 r1 = *(const float2*)(res1 + off);
                    float2 r2 = *(const float2*)(res2 + off);
                    *(float2*)((float*)outp + off) =
                        make_float2(v0 + r1.x + r2.x, v1 + r1.y + r2.y);
                } else {
                    float g0 = 0.5f * v0 * (1.0f + erff(v0 * 0.70710678118654752f));
                    float g1 = 0.5f * v1 * (1.0f + erff(v1 * 0.70710678118654752f));
                    *(__half2*)((__half*)outp + off) = __floats2half2_rn(g0, g1);
                }
            }
        }
    }
}

// =================== launcher ===================
extern "C" void kernel_launch(void* const* d_in, const int* in_sizes, int n_in,
                              void* d_out, int out_size) {
    const float* x       = (const float*)d_in[0];
    const float* decay   = (const float*)d_in[1];
    const float* W_out   = (const float*)d_in[2];
    const float* b_out   = (const float*)d_in[3];
    const float* conv_w  = (const float*)d_in[4];
    const float* conv_b  = (const float*)d_in[5];
    const float* ln1_g   = (const float*)d_in[6];
    const float* ln1_b   = (const float*)d_in[7];
    const float* ln2_g   = (const float*)d_in[8];
    const float* ln2_b   = (const float*)d_in[9];
    const float* W1      = (const float*)d_in[10];
    const float* b1      = (const float*)d_in[11];
    const float* W2      = (const float*)d_in[12];
    const float* b2      = (const float*)d_in[13];
    float* out = (float*)d_out;

    float *x1, *yloc, *lend, *carry;
    __half *xnh, *ssh, *xn2h, *hh, *wouth, *w1h, *w2h;
    cudaGetSymbolAddress((void**)&xnh,   g_xnh);
    cudaGetSymbolAddress((void**)&x1,    g_x1);
    cudaGetSymbolAddress((void**)&yloc,  g_yloc);
    cudaGetSymbolAddress((void**)&lend,  g_lend);
    cudaGetSymbolAddress((void**)&carry, g_carry);
    cudaGetSymbolAddress((void**)&ssh,   g_ssh);
    cudaGetSymbolAddress((void**)&xn2h,  g_xn2h);
    cudaGetSymbolAddress((void**)&hh,    g_hh);
    cudaGetSymbolAddress((void**)&wouth, g_wouth);
    cudaGetSymbolAddress((void**)&w1h,   g_w1h);
    cudaGetSymbolAddress((void**)&w2h,   g_w2h);

    cudaFuncSetAttribute(gemm_mma<0>, cudaFuncAttributeMaxDynamicSharedMemorySize, GEMM_SMEM);
    cudaFuncSetAttribute(gemm_mma<1>, cudaFuncAttributeMaxDynamicSharedMemorySize, GEMM_SMEM);
    cudaFuncSetAttribute(gemm_mma<2>, cudaFuncAttributeMaxDynamicSharedMemorySize, GEMM_SMEM);

    // weight conversion (single launch)
    wconv<<<(N0 + N1 + N2 + 255) / 256, 256>>>(W_out, W1, W2, wouth, w1h, w2h);

    // 1) xn = LN1(x)  (fp16)
    ln_kernel<<<NTOK / 8, 256>>>(x, ln1_g, ln1_b, xnh);

    // 2) retention scan (chunked) + fused depthwise conv
    scan_partial<<<(Bz * CH * Dz) / 256, 256>>>(xnh, decay, lend);
    scan_carry<<<(Bz * Dz) / 256, 256>>>(lend, decay, carry);
    scan_final_fused<<<(Bz * CH * Dz) / 256, 256>>>(xnh, decay, carry,
                                                    conv_w, conv_b, ssh, yloc);

    // 3) x1 = x + yloc + ss @ W_out^T + b_out
    gemm_mma<2><<<(NTOK / 128) * (Dz / 256), 256, GEMM_SMEM>>>(
        ssh, wouth, b_out, NTOK, Dz, Dz, x, yloc, x1);

    // 4) xn2 = LN2(x1)  (fp16)
    ln_kernel<<<NTOK / 8, 256>>>(x1, ln2_g, ln2_b, xn2h);

    // 5) h = gelu(xn2 @ W1^T + b1)  (fp16 out)
    gemm_mma<1><<<(NTOK / 128) * (HIDz / 256), 256, GEMM_SMEM>>>(
        xn2h, w1h, b1, NTOK, HIDz, Dz, nullptr, nullptr, hh);

    // 6) out = x1 + h @ W2^T + b2
    gemm_mma<0><<<(NTOK / 128) * (Dz / 256), 256, GEMM_SMEM>>>(
        hh, w2h, b2, NTOK, Dz, HIDz, x1, nullptr, out);
}